// round 10
// baseline (speedup 1.0000x reference)
#include <cuda_runtime.h>

#define B_ 16
#define C_ 512
#define N_ 4096
#define K_ 32

// 8 MB scratch for softmax weights w[b][n][k]
__device__ __align__(16) float g_w[B_ * N_ * K_];

typedef unsigned long long ull;

// ---------------- packed f32x2 helpers ----------------
__device__ __forceinline__ ull pk2(float a, float b) {
    ull r;
    asm("mov.b64 %0, {%1, %2};" : "=l"(r) : "f"(a), "f"(b));
    return r;
}
__device__ __forceinline__ void ffma2(ull &d, ull a, ull b) {
    asm("fma.rn.f32x2 %0, %1, %2, %0;" : "+l"(d) : "l"(a), "l"(b));
}
__device__ __forceinline__ void upk2(ull v, float &a, float &b) {
    asm("mov.b64 {%0, %1}, %2;" : "=f"(a), "=f"(b) : "l"(v));
}
__device__ __forceinline__ ull lds_u64(unsigned addr) {
    ull v;
    asm volatile("ld.shared.b64 %0, [%1];" : "=l"(v) : "r"(addr));
    return v;
}
__device__ __forceinline__ float4 lds128(unsigned addr) {
    float4 v;
    asm volatile("ld.shared.v4.f32 {%0,%1,%2,%3}, [%4];"
                 : "=f"(v.x), "=f"(v.y), "=f"(v.z), "=f"(v.w) : "r"(addr));
    return v;
}

// ================= kernel 1: assign (xc gemm + softmax -> g_w, zeroes out) ==============
// 128 tokens/block, 256 threads = 8 warps (4 k-groups x 2 token-halves).
// Thread tile: 2 tokens (1 pair at 64*th+2L) x 8 k -> acc = 8 packed pairs.
// smem words:
//   [0,4224)     xs[c 0..31][n 0..127] (4096)  | later sxc[tok 0..127][k, pitch 33] (4224)
//   [4224,5376)  cws[c 0..31][k, pitch 36]
//   [5376,6400)  sqarr[8][128]  (xsq partials)
//   [6400,6432)  sa[32]   [6432,6464) sd[32]
#define XSA 0
#define CWSA 4224
#define SQO 5376
#define SAO 6400
#define SDO 6432
#define ASM_WORDS 6464

__global__ void __launch_bounds__(256) assign_kernel(const float *__restrict__ x,
                                                     const float *__restrict__ cw,
                                                     const float *__restrict__ scale,
                                                     float *__restrict__ out) {
    __shared__ __align__(16) float sm[ASM_WORDS];
    const int t = threadIdx.x;

    // fold output zeroing: 262144 floats = 65536 float4 over 512 blocks
    if (t < 128)
        reinterpret_cast<float4 *>(out)[blockIdx.x * 128 + t] = make_float4(0.f, 0.f, 0.f, 0.f);

    const int T0 = blockIdx.x * 128;                    // global token base
    const float *xb = x + (size_t)(T0 >> 12) * C_ * N_ + (T0 & (N_ - 1));
    const int L = t & 31;
    const int wmid = t >> 5;                            // warp id
    const int kg = wmid & 3;                            // k-group (8 k)
    const int th = wmid >> 2;                           // token half
    const int q = t & 31;                               // x loader: fixed n-quad (tokens 4q..4q+3)
    const int kA = t >> 3;                              // cw loader: k row (0..31)
    const int c4 = (t & 7) * 4;                         // cw loader: c quad

    ull acc[8];
#pragma unroll
    for (int m = 0; m < 8; ++m) acc[m] = 0ull;
    float4 xsq4 = make_float4(0.f, 0.f, 0.f, 0.f);
    float csq = 0.f;

    const unsigned smb = (unsigned)__cvta_generic_to_shared(sm);

#pragma unroll 1
    for (int cc = 0; cc < C_; cc += 32) {
        __syncthreads();
        // stage x chunk [32 c][128 n]: 4 float4/thread, fixed q per thread -> xsq partials
#pragma unroll
        for (int j = 0; j < 4; ++j) {
            const int c = (t >> 5) + 8 * j;
            float4 v = *reinterpret_cast<const float4 *>(xb + (size_t)(cc + c) * N_ + 4 * q);
            *reinterpret_cast<float4 *>(&sm[XSA + c * 128 + 4 * q]) = v;
            xsq4.x = fmaf(v.x, v.x, xsq4.x);
            xsq4.y = fmaf(v.y, v.y, xsq4.y);
            xsq4.z = fmaf(v.z, v.z, xsq4.z);
            xsq4.w = fmaf(v.w, v.w, xsq4.w);
        }
        // stage cw chunk transposed [32 c][32 k] pitch 36 (+ csq partial)
        {
            float4 a = *reinterpret_cast<const float4 *>(cw + (size_t)kA * C_ + cc + c4);
            sm[CWSA + (c4 + 0) * 36 + kA] = a.x;
            sm[CWSA + (c4 + 1) * 36 + kA] = a.y;
            sm[CWSA + (c4 + 2) * 36 + kA] = a.z;
            sm[CWSA + (c4 + 3) * 36 + kA] = a.w;
            csq = fmaf(a.x, a.x, csq); csq = fmaf(a.y, a.y, csq);
            csq = fmaf(a.z, a.z, csq); csq = fmaf(a.w, a.w, csq);
        }
        __syncthreads();

#pragma unroll 4
        for (int c = 0; c < 32; ++c) {
            ull xp = lds_u64(smb + (unsigned)((XSA + c * 128 + 64 * th + 2 * L) * 4));
            float4 w0 = lds128(smb + (unsigned)((CWSA + c * 36 + 8 * kg) * 4));
            float4 w1 = lds128(smb + (unsigned)((CWSA + c * 36 + 8 * kg + 4) * 4));
            ffma2(acc[0], xp, pk2(w0.x, w0.x));
            ffma2(acc[1], xp, pk2(w0.y, w0.y));
            ffma2(acc[2], xp, pk2(w0.z, w0.z));
            ffma2(acc[3], xp, pk2(w0.w, w0.w));
            ffma2(acc[4], xp, pk2(w1.x, w1.x));
            ffma2(acc[5], xp, pk2(w1.y, w1.y));
            ffma2(acc[6], xp, pk2(w1.z, w1.z));
            ffma2(acc[7], xp, pk2(w1.w, w1.w));
        }
    }
    __syncthreads();   // mainloop xs reads done before sxc overwrite

    // exchange xc -> sxc[tok][k] pitch 33
    {
        const int tok = 64 * th + 2 * L;
#pragma unroll
        for (int kk = 0; kk < 8; ++kk) {
            float lo, hi;
            upk2(acc[kk], lo, hi);
            sm[XSA + tok * 33 + 8 * kg + kk] = lo;
            sm[XSA + (tok + 1) * 33 + 8 * kg + kk] = hi;
        }
    }
    // xsq partials: 8 disjoint c-subsets (r = t>>5) per token quad
    *reinterpret_cast<float4 *>(&sm[SQO + (t >> 5) * 128 + 4 * q]) = xsq4;
    // csq: 8 consecutive lanes share k -> octet shfl reduce
#pragma unroll
    for (int d = 1; d < 8; d <<= 1) csq += __shfl_xor_sync(0xffffffffu, csq, d);
    if ((t & 7) == 0) {
        float s = scale[kA];
        sm[SAO + kA] = s;
        sm[SDO + kA] = s * csq;
    }
    __syncthreads();

    // softmax: thread t<128 handles token t, writes w back into sxc row
    if (t < 128) {
        float xsq = 0.f;
#pragma unroll
        for (int r = 0; r < 8; ++r) xsq += sm[SQO + r * 128 + t];
        float l[K_];
        float mx = -1e30f;
#pragma unroll
        for (int k = 0; k < K_; ++k) {
            float lv = sm[SAO + k] * (xsq - 2.0f * sm[XSA + t * 33 + k]) + sm[SDO + k];
            l[k] = lv;
            mx = fmaxf(mx, lv);
        }
        float s = 0.f;
#pragma unroll
        for (int k = 0; k < K_; ++k) {
            float e = __expf(l[k] - mx);
            l[k] = e;
            s += e;
        }
        float inv = 1.0f / s;
#pragma unroll
        for (int k = 0; k < K_; ++k) sm[XSA + t * 33 + k] = l[k] * inv;
    }
    __syncthreads();

    // coalesced copy sxc -> g_w (4096 floats)
    float *gw = g_w + (size_t)T0 * K_;
#pragma unroll
    for (int i = 0; i < 16; ++i) {
        const int f = t + 256 * i;
        gw[f] = sm[XSA + (f >> 5) * 33 + (f & 31)];
    }
}

// ================= kernel 2: aggregate (enc gemm + wsum fold + REDG) ==============
// grid (16 n-splits, 16 b, 2 c-tiles), 256 threads = 8 warps (4 k-groups x 2 c-halves).
// Thread tile: 4 c (2 pairs at 128*ch + 64j + 2L) x 8 k -> 16 packed accumulators.
// dyn smem words: ws[256][32]=8192 | xs[16][258]=4128 | wpart 1024 | wsf 32 -> 13376 w = 53.5 KB
#define WS0 0
#define XS0 8192
#define WP0 12320
#define WF0 13344
#define AGG_WORDS 13376
#define XP 258

__global__ void __launch_bounds__(256) aggregate_kernel(const float *__restrict__ x,
                                                        const float *__restrict__ cw,
                                                        float *__restrict__ out) {
    extern __shared__ float sg[];
    const int t = threadIdx.x;
    const int b = blockIdx.y;
    const int n0 = blockIdx.x * 256;
    const int cbase = blockIdx.z * 256;
    const int L = t & 31;
    const int wmid = t >> 5;
    const int kg = wmid & 3;
    const int ch = wmid >> 2;          // c-half within the 256-c tile

    // stage w chunk [256 n][32 k] + wsum partial (fixed k-quad = t&7)
    {
        const float4 *gw4 = reinterpret_cast<const float4 *>(g_w + ((size_t)b * N_ + n0) * K_);
        float4 wsum4 = make_float4(0.f, 0.f, 0.f, 0.f);
#pragma unroll
        for (int j = 0; j < 8; ++j) {
            const int flat = t + 256 * j;
            float4 v = gw4[flat];
            *reinterpret_cast<float4 *>(&sg[WS0 + 4 * flat]) = v;
            wsum4.x += v.x; wsum4.y += v.y; wsum4.z += v.z; wsum4.w += v.w;
        }
        *reinterpret_cast<float4 *>(&sg[WP0 + 4 * t]) = wsum4;
    }

    ull acc[16];
#pragma unroll
    for (int m = 0; m < 16; ++m) acc[m] = 0ull;

    const unsigned smb = (unsigned)__cvta_generic_to_shared(sg);
    const float *xg = x + ((size_t)b * C_ + cbase) * N_ + n0;

#pragma unroll 1
    for (int s = 0; s < 16; ++s) {
        __syncthreads();
        // stage x subtile transposed: 256 c x 16 n -> xs[n][c] pitch 258 (conflict-free STS)
#pragma unroll
        for (int j = 0; j < 4; ++j) {
            const int flat = t + 256 * j;
            const int c = flat >> 2;
            const int q = flat & 3;
            float4 v = *reinterpret_cast<const float4 *>(xg + (size_t)c * N_ + s * 16 + 4 * q);
            sg[XS0 + (4 * q + 0) * XP + c] = v.x;
            sg[XS0 + (4 * q + 1) * XP + c] = v.y;
            sg[XS0 + (4 * q + 2) * XP + c] = v.z;
            sg[XS0 + (4 * q + 3) * XP + c] = v.w;
        }
        __syncthreads();

#pragma unroll 4
        for (int nn = 0; nn < 16; ++nn) {
            const int n = s * 16 + nn;
            ull xp0 = lds_u64(smb + (unsigned)((XS0 + nn * XP + 128 * ch + 2 * L) * 4));
            ull xp1 = lds_u64(smb + (unsigned)((XS0 + nn * XP + 128 * ch + 64 + 2 * L) * 4));
            float4 w0 = lds128(smb + (unsigned)((WS0 + n * 32 + 8 * kg) * 4));
            float4 w1 = lds128(smb + (unsigned)((WS0 + n * 32 + 8 * kg + 4) * 4));
            ull wv[8] = {pk2(w0.x, w0.x), pk2(w0.y, w0.y), pk2(w0.z, w0.z), pk2(w0.w, w0.w),
                         pk2(w1.x, w1.x), pk2(w1.y, w1.y), pk2(w1.z, w1.z), pk2(w1.w, w1.w)};
#pragma unroll
            for (int kk = 0; kk < 8; ++kk) {
                ffma2(acc[kk], xp0, wv[kk]);
                ffma2(acc[8 + kk], xp1, wv[kk]);
            }
        }
    }

    // reduce wsum partials (32 partials per k-quad)
    __syncthreads();
    if (t < 8) {
        float4 s4 = make_float4(0.f, 0.f, 0.f, 0.f);
#pragma unroll
        for (int j = 0; j < 32; ++j) {
            float4 v = *reinterpret_cast<const float4 *>(&sg[WP0 + 4 * (t + 8 * j)]);
            s4.x += v.x; s4.y += v.y; s4.z += v.z; s4.w += v.w;
        }
        *reinterpret_cast<float4 *>(&sg[WF0 + 4 * t]) = s4;
    }
    __syncthreads();

    // epilogue: fold -wsum_partial*cw, reduce to global (coalesced-pair red.global.f32)
    float *ob = out + (size_t)b * K_ * C_;
#pragma unroll
    for (int kk = 0; kk < 8; ++kk) {
        const int k = 8 * kg + kk;
        const float wk = sg[WF0 + k];
#pragma unroll
        for (int j = 0; j < 2; ++j) {
            const int c = cbase + 128 * ch + 64 * j + 2 * L;
            float a0, a1;
            upk2(acc[j * 8 + kk], a0, a1);
            float2 cv = *reinterpret_cast<const float2 *>(&cw[(size_t)k * C_ + c]);
            atomicAdd(&ob[(size_t)k * C_ + c], a0 - wk * cv.x);
            atomicAdd(&ob[(size_t)k * C_ + c + 1], a1 - wk * cv.y);
        }
    }
}

extern "C" void kernel_launch(void *const *d_in, const int *in_sizes, int n_in,
                              void *d_out, int out_size) {
    const float *x = (const float *)d_in[0];
    const float *cwp = (const float *)d_in[1];
    const float *scale = (const float *)d_in[2];
    float *out = (float *)d_out;

    cudaFuncSetAttribute(aggregate_kernel, cudaFuncAttributeMaxDynamicSharedMemorySize,
                         AGG_WORDS * (int)sizeof(float));

    assign_kernel<<<(B_ * N_) / 128, 256>>>(x, cwp, scale, out);
    aggregate_kernel<<<dim3(N_ / 256, B_, 2), 256, AGG_WORDS * sizeof(float)>>>(x, cwp, out);
}

// round 12
// speedup vs baseline: 1.0011x; 1.0011x over previous
#include <cuda_runtime.h>

#define B_ 16
#define C_ 512
#define N_ 4096
#define K_ 32

// 8 MB scratch for softmax weights w[b][n][k]
__device__ __align__(16) float g_w[B_ * N_ * K_];

typedef unsigned long long ull;

// ---------------- packed f32x2 helpers ----------------
__device__ __forceinline__ ull pk2(float a, float b) {
    ull r;
    asm("mov.b64 %0, {%1, %2};" : "=l"(r) : "f"(a), "f"(b));
    return r;
}
__device__ __forceinline__ void ffma2(ull &d, ull a, ull b) {
    asm("fma.rn.f32x2 %0, %1, %2, %0;" : "+l"(d) : "l"(a), "l"(b));
}
__device__ __forceinline__ void upk2(ull v, float &a, float &b) {
    asm("mov.b64 {%0, %1}, %2;" : "=f"(a), "=f"(b) : "l"(v));
}
__device__ __forceinline__ ull lds_u64(unsigned addr) {
    ull v;
    asm volatile("ld.shared.b64 %0, [%1];" : "=l"(v) : "r"(addr));
    return v;
}
__device__ __forceinline__ float4 lds128(unsigned addr) {
    float4 v;
    asm volatile("ld.shared.v4.f32 {%0,%1,%2,%3}, [%4];"
                 : "=f"(v.x), "=f"(v.y), "=f"(v.z), "=f"(v.w) : "r"(addr));
    return v;
}

// ================= kernel 1: assign (xc gemm + softmax -> g_w, zeroes out) ==============
// 128 tokens/block, 256 threads = 8 warps (4 k-groups x 2 token-halves).
// Thread tile: 2 tokens (1 pair at 64*th+2L) x 8 k -> acc = 8 packed pairs.
// smem words:
//   [0,4224)     xs[c 0..31][n 0..127] (4096)  | later sxc[tok 0..127][k, pitch 33] (4224)
//   [4224,5376)  cws[c 0..31][k, pitch 36]
//   [5376,6400)  sqarr[8][128]  (xsq partials)
//   [6400,6432)  sa[32]   [6432,6464) sd[32]
#define XSA 0
#define CWSA 4224
#define SQO 5376
#define SAO 6400
#define SDO 6432
#define ASM_WORDS 6464

__global__ void __launch_bounds__(256) assign_kernel(const float *__restrict__ x,
                                                     const float *__restrict__ cw,
                                                     const float *__restrict__ scale,
                                                     float *__restrict__ out) {
    __shared__ __align__(16) float sm[ASM_WORDS];
    const int t = threadIdx.x;

    // fold output zeroing: 262144 floats = 65536 float4 over 512 blocks
    if (t < 128)
        reinterpret_cast<float4 *>(out)[blockIdx.x * 128 + t] = make_float4(0.f, 0.f, 0.f, 0.f);

    const int T0 = blockIdx.x * 128;                    // global token base
    const float *xb = x + (size_t)(T0 >> 12) * C_ * N_ + (T0 & (N_ - 1));
    const int L = t & 31;
    const int wmid = t >> 5;                            // warp id
    const int kg = wmid & 3;                            // k-group (8 k)
    const int th = wmid >> 2;                           // token half
    const int q = t & 31;                               // x loader: fixed n-quad (tokens 4q..4q+3)
    const int kA = t >> 3;                              // cw loader: k row (0..31)
    const int c4 = (t & 7) * 4;                         // cw loader: c quad

    ull acc[8];
#pragma unroll
    for (int m = 0; m < 8; ++m) acc[m] = 0ull;
    float4 xsq4 = make_float4(0.f, 0.f, 0.f, 0.f);
    float csq = 0.f;

    const unsigned smb = (unsigned)__cvta_generic_to_shared(sm);

#pragma unroll 1
    for (int cc = 0; cc < C_; cc += 32) {
        __syncthreads();
        // stage x chunk [32 c][128 n]: 4 float4/thread, fixed q per thread -> xsq partials
#pragma unroll
        for (int j = 0; j < 4; ++j) {
            const int c = (t >> 5) + 8 * j;
            float4 v = *reinterpret_cast<const float4 *>(xb + (size_t)(cc + c) * N_ + 4 * q);
            *reinterpret_cast<float4 *>(&sm[XSA + c * 128 + 4 * q]) = v;
            xsq4.x = fmaf(v.x, v.x, xsq4.x);
            xsq4.y = fmaf(v.y, v.y, xsq4.y);
            xsq4.z = fmaf(v.z, v.z, xsq4.z);
            xsq4.w = fmaf(v.w, v.w, xsq4.w);
        }
        // stage cw chunk transposed [32 c][32 k] pitch 36 (+ csq partial)
        {
            float4 a = *reinterpret_cast<const float4 *>(cw + (size_t)kA * C_ + cc + c4);
            sm[CWSA + (c4 + 0) * 36 + kA] = a.x;
            sm[CWSA + (c4 + 1) * 36 + kA] = a.y;
            sm[CWSA + (c4 + 2) * 36 + kA] = a.z;
            sm[CWSA + (c4 + 3) * 36 + kA] = a.w;
            csq = fmaf(a.x, a.x, csq); csq = fmaf(a.y, a.y, csq);
            csq = fmaf(a.z, a.z, csq); csq = fmaf(a.w, a.w, csq);
        }
        __syncthreads();

#pragma unroll 4
        for (int c = 0; c < 32; ++c) {
            ull xp = lds_u64(smb + (unsigned)((XSA + c * 128 + 64 * th + 2 * L) * 4));
            float4 w0 = lds128(smb + (unsigned)((CWSA + c * 36 + 8 * kg) * 4));
            float4 w1 = lds128(smb + (unsigned)((CWSA + c * 36 + 8 * kg + 4) * 4));
            ffma2(acc[0], xp, pk2(w0.x, w0.x));
            ffma2(acc[1], xp, pk2(w0.y, w0.y));
            ffma2(acc[2], xp, pk2(w0.z, w0.z));
            ffma2(acc[3], xp, pk2(w0.w, w0.w));
            ffma2(acc[4], xp, pk2(w1.x, w1.x));
            ffma2(acc[5], xp, pk2(w1.y, w1.y));
            ffma2(acc[6], xp, pk2(w1.z, w1.z));
            ffma2(acc[7], xp, pk2(w1.w, w1.w));
        }
    }
    __syncthreads();   // mainloop xs reads done before sxc overwrite

    // exchange xc -> sxc[tok][k] pitch 33
    {
        const int tok = 64 * th + 2 * L;
#pragma unroll
        for (int kk = 0; kk < 8; ++kk) {
            float lo, hi;
            upk2(acc[kk], lo, hi);
            sm[XSA + tok * 33 + 8 * kg + kk] = lo;
            sm[XSA + (tok + 1) * 33 + 8 * kg + kk] = hi;
        }
    }
    // xsq partials: 8 disjoint c-subsets (r = t>>5) per token quad
    *reinterpret_cast<float4 *>(&sm[SQO + (t >> 5) * 128 + 4 * q]) = xsq4;
    // csq: 8 consecutive lanes share k -> octet shfl reduce
#pragma unroll
    for (int d = 1; d < 8; d <<= 1) csq += __shfl_xor_sync(0xffffffffu, csq, d);
    if ((t & 7) == 0) {
        float s = scale[kA];
        sm[SAO + kA] = s;
        sm[SDO + kA] = s * csq;
    }
    __syncthreads();

    // softmax: thread t<128 handles token t, writes w back into sxc row
    if (t < 128) {
        float xsq = 0.f;
#pragma unroll
        for (int r = 0; r < 8; ++r) xsq += sm[SQO + r * 128 + t];
        float l[K_];
        float mx = -1e30f;
#pragma unroll
        for (int k = 0; k < K_; ++k) {
            float lv = sm[SAO + k] * (xsq - 2.0f * sm[XSA + t * 33 + k]) + sm[SDO + k];
            l[k] = lv;
            mx = fmaxf(mx, lv);
        }
        float s = 0.f;
#pragma unroll
        for (int k = 0; k < K_; ++k) {
            float e = __expf(l[k] - mx);
            l[k] = e;
            s += e;
        }
        float inv = 1.0f / s;
#pragma unroll
        for (int k = 0; k < K_; ++k) sm[XSA + t * 33 + k] = l[k] * inv;
    }
    __syncthreads();

    // coalesced copy sxc -> g_w (4096 floats)
    float *gw = g_w + (size_t)T0 * K_;
#pragma unroll
    for (int i = 0; i < 16; ++i) {
        const int f = t + 256 * i;
        gw[f] = sm[XSA + (f >> 5) * 33 + (f & 31)];
    }
}

// ================= kernel 2: aggregate (enc gemm + wsum fold + REDG) ==============
// grid (16 n-splits, 16 b, 2 c-tiles), 256 threads = 8 warps (4 k-groups x 2 c-halves).
// Thread tile: 4 c (2 pairs at 128*ch + 64j + 2L) x 8 k -> 16 packed accumulators.
// dyn smem words: ws[256][32]=8192 | xs[16][258]=4128 | wpart 1024 | wsf 32 -> 13376 w = 53.5 KB
#define WS0 0
#define XS0 8192
#define WP0 12320
#define WF0 13344
#define AGG_WORDS 13376
#define XP 258

__global__ void __launch_bounds__(256) aggregate_kernel(const float *__restrict__ x,
                                                        const float *__restrict__ cw,
                                                        float *__restrict__ out) {
    extern __shared__ float sg[];
    const int t = threadIdx.x;
    const int b = blockIdx.y;
    const int n0 = blockIdx.x * 256;
    const int cbase = blockIdx.z * 256;
    const int L = t & 31;
    const int wmid = t >> 5;
    const int kg = wmid & 3;
    const int ch = wmid >> 2;          // c-half within the 256-c tile

    // stage w chunk [256 n][32 k] + wsum partial (fixed k-quad = t&7)
    {
        const float4 *gw4 = reinterpret_cast<const float4 *>(g_w + ((size_t)b * N_ + n0) * K_);
        float4 wsum4 = make_float4(0.f, 0.f, 0.f, 0.f);
#pragma unroll
        for (int j = 0; j < 8; ++j) {
            const int flat = t + 256 * j;
            float4 v = gw4[flat];
            *reinterpret_cast<float4 *>(&sg[WS0 + 4 * flat]) = v;
            wsum4.x += v.x; wsum4.y += v.y; wsum4.z += v.z; wsum4.w += v.w;
        }
        *reinterpret_cast<float4 *>(&sg[WP0 + 4 * t]) = wsum4;
    }

    ull acc[16];
#pragma unroll
    for (int m = 0; m < 16; ++m) acc[m] = 0ull;

    const unsigned smb = (unsigned)__cvta_generic_to_shared(sg);
    const float *xg = x + ((size_t)b * C_ + cbase) * N_ + n0;

#pragma unroll 1
    for (int s = 0; s < 16; ++s) {
        __syncthreads();
        // stage x subtile transposed: 256 c x 16 n -> xs[n][c] pitch 258 (conflict-free STS)
#pragma unroll
        for (int j = 0; j < 4; ++j) {
            const int flat = t + 256 * j;
            const int c = flat >> 2;
            const int q = flat & 3;
            float4 v = *reinterpret_cast<const float4 *>(xg + (size_t)c * N_ + s * 16 + 4 * q);
            sg[XS0 + (4 * q + 0) * XP + c] = v.x;
            sg[XS0 + (4 * q + 1) * XP + c] = v.y;
            sg[XS0 + (4 * q + 2) * XP + c] = v.z;
            sg[XS0 + (4 * q + 3) * XP + c] = v.w;
        }
        __syncthreads();

#pragma unroll 4
        for (int nn = 0; nn < 16; ++nn) {
            const int n = s * 16 + nn;
            ull xp0 = lds_u64(smb + (unsigned)((XS0 + nn * XP + 128 * ch + 2 * L) * 4));
            ull xp1 = lds_u64(smb + (unsigned)((XS0 + nn * XP + 128 * ch + 64 + 2 * L) * 4));
            float4 w0 = lds128(smb + (unsigned)((WS0 + n * 32 + 8 * kg) * 4));
            float4 w1 = lds128(smb + (unsigned)((WS0 + n * 32 + 8 * kg + 4) * 4));
            ull wv[8] = {pk2(w0.x, w0.x), pk2(w0.y, w0.y), pk2(w0.z, w0.z), pk2(w0.w, w0.w),
                         pk2(w1.x, w1.x), pk2(w1.y, w1.y), pk2(w1.z, w1.z), pk2(w1.w, w1.w)};
#pragma unroll
            for (int kk = 0; kk < 8; ++kk) {
                ffma2(acc[kk], xp0, wv[kk]);
                ffma2(acc[8 + kk], xp1, wv[kk]);
            }
        }
    }

    // reduce wsum partials (32 partials per k-quad)
    __syncthreads();
    if (t < 8) {
        float4 s4 = make_float4(0.f, 0.f, 0.f, 0.f);
#pragma unroll
        for (int j = 0; j < 32; ++j) {
            float4 v = *reinterpret_cast<const float4 *>(&sg[WP0 + 4 * (t + 8 * j)]);
            s4.x += v.x; s4.y += v.y; s4.z += v.z; s4.w += v.w;
        }
        *reinterpret_cast<float4 *>(&sg[WF0 + 4 * t]) = s4;
    }
    __syncthreads();

    // epilogue: fold -wsum_partial*cw, reduce to global (coalesced-pair red.global.f32)
    float *ob = out + (size_t)b * K_ * C_;
#pragma unroll
    for (int kk = 0; kk < 8; ++kk) {
        const int k = 8 * kg + kk;
        const float wk = sg[WF0 + k];
#pragma unroll
        for (int j = 0; j < 2; ++j) {
            const int c = cbase + 128 * ch + 64 * j + 2 * L;
            float a0, a1;
            upk2(acc[j * 8 + kk], a0, a1);
            float2 cv = *reinterpret_cast<const float2 *>(&cw[(size_t)k * C_ + c]);
            atomicAdd(&ob[(size_t)k * C_ + c], a0 - wk * cv.x);
            atomicAdd(&ob[(size_t)k * C_ + c + 1], a1 - wk * cv.y);
        }
    }
}

extern "C" void kernel_launch(void *const *d_in, const int *in_sizes, int n_in,
                              void *d_out, int out_size) {
    const float *x = (const float *)d_in[0];
    const float *cwp = (const float *)d_in[1];
    const float *scale = (const float *)d_in[2];
    float *out = (float *)d_out;

    cudaFuncSetAttribute(aggregate_kernel, cudaFuncAttributeMaxDynamicSharedMemorySize,
                         AGG_WORDS * (int)sizeof(float));

    assign_kernel<<<(B_ * N_) / 128, 256>>>(x, cwp, scale, out);
    aggregate_kernel<<<dim3(N_ / 256, B_, 2), 256, AGG_WORDS * sizeof(float)>>>(x, cwp, out);
}